// round 8
// baseline (speedup 1.0000x reference)
#include <cuda_runtime.h>
#include <stdint.h>

#define NB     32
#define CIN    256
#define HDIM   56
#define HW     3136
#define PIXI   100352          // 32*56*56 interior pixels
#define OC     256
#define HP     58
#define IMGP   (HP*HP)         // 3364
#define NPAD   (NB*IMGP)       // 107648 padded pixels = 841*128
#define GUARD  72
#define XROWS  (NPAD + 2*GUARD)
#define KTOT   2304
#define MT     128
#define NTILES (NPAD/MT)       // 841
#define PROWS  (NPAD + 16)     // plane rows incl 8-row guards
#define NCHUNK 9               // one tap per chunk, K=256
#define CH_A   32768           // 128 rows * 256B
#define CH_B   32768           // 128 oc  * 256B
#define STG    (CH_A + CH_B)   // 65536
#define STAGES 3
#define SMEMG  (STAGES*STG)    // 196608
#define EPI_STRIDE 132

// ---- device scratch (static allocation: allowed) ----
__device__ float g_alpha[NB];
__device__ float g_m[OC];
__device__ float g_part[NB*16];
__device__ __align__(256) signed char g_xs[(size_t)XROWS*256];           // padded signs
__device__ __align__(256) signed char g_xp[(size_t)3*PROWS*256];         // 3 dh-shifted swizzled planes (~83MB)
__device__ __align__(256) signed char g_wsp[(size_t)NCHUNK*2*128*256];   // weight planes [tap][g][o][256B]

// ===================== helpers =====================
__device__ __forceinline__ uint32_t smem_u32(const void* p) {
    uint32_t a;
    asm("{ .reg .u64 t; cvta.to.shared.u64 t, %1; cvt.u32.u64 %0, t; }" : "=r"(a) : "l"(p));
    return a;
}
__device__ __forceinline__ void mbar_init(uint32_t a, uint32_t cnt) {
    asm volatile("mbarrier.init.shared.b64 [%0], %1;" :: "r"(a), "r"(cnt) : "memory");
}
__device__ __forceinline__ void mbar_expect_tx(uint32_t a, uint32_t tx) {
    asm volatile("mbarrier.arrive.expect_tx.shared.b64 _, [%0], %1;" :: "r"(a), "r"(tx) : "memory");
}
__device__ __forceinline__ void mbar_arrive(uint32_t a) {
    asm volatile("mbarrier.arrive.shared.b64 _, [%0];" :: "r"(a) : "memory");
}
__device__ __forceinline__ void mbar_wait(uint32_t a, uint32_t ph) {
    asm volatile(
        "{ .reg .pred P;\n"
        "WL_%=: mbarrier.try_wait.parity.acquire.cta.shared::cta.b64 P, [%0], %1, 0x989680;\n"
        "@P bra WD_%=;\n"
        "bra WL_%=;\n"
        "WD_%=: }"
        :: "r"(a), "r"(ph) : "memory");
}
__device__ __forceinline__ void bulkcp(uint32_t dst, const void* src, uint32_t bytes, uint32_t mbar) {
    asm volatile("cp.async.bulk.shared::cluster.global.mbarrier::complete_tx::bytes [%0], [%1], %2, [%3];"
                 :: "r"(dst), "l"(src), "r"(bytes), "r"(mbar) : "memory");
}
__device__ __forceinline__ void ldsm4(uint32_t (&r)[4], uint32_t addr) {
    asm volatile("ldmatrix.sync.aligned.m8n8.x4.shared.b16 {%0,%1,%2,%3}, [%4];"
                 : "=r"(r[0]), "=r"(r[1]), "=r"(r[2]), "=r"(r[3]) : "r"(addr));
}
__device__ __forceinline__ void imma(int* c, const uint32_t* a, uint32_t b0, uint32_t b1) {
    asm volatile("mma.sync.aligned.m16n8k32.row.col.s32.s8.s8.s32 "
                 "{%0,%1,%2,%3}, {%4,%5,%6,%7}, {%8,%9}, {%0,%1,%2,%3};"
                 : "+r"(c[0]), "+r"(c[1]), "+r"(c[2]), "+r"(c[3])
                 : "r"(a[0]), "r"(a[1]), "r"(a[2]), "r"(a[3]), "r"(b0), "r"(b1));
}

// ===================== prep kernels =====================
__global__ void k_absmean_x(const float* __restrict__ x) {
    int n = blockIdx.x >> 4;
    int chunk = blockIdx.x & 15;
    const float4* xv = (const float4*)x + (size_t)n * 200704 + (size_t)chunk * 12544;
    float s = 0.f;
    for (int i = threadIdx.x; i < 12544; i += 256) {
        float4 v = xv[i];
        s += fabsf(v.x) + fabsf(v.y) + fabsf(v.z) + fabsf(v.w);
    }
    __shared__ float sh[8];
    #pragma unroll
    for (int d = 16; d > 0; d >>= 1) s += __shfl_down_sync(0xffffffffu, s, d);
    if ((threadIdx.x & 31) == 0) sh[threadIdx.x >> 5] = s;
    __syncthreads();
    if (threadIdx.x == 0) {
        float t = 0.f;
        #pragma unroll
        for (int i = 0; i < 8; i++) t += sh[i];
        g_part[blockIdx.x] = t;
    }
}
__global__ void k_alpha() {
    int n = threadIdx.x;
    float s = 0.f;
    #pragma unroll
    for (int i = 0; i < 16; i++) s += g_part[n * 16 + i];
    float a = 2.f * s / (float)(CIN * HW);
    g_alpha[n] = fmaxf(a, 1e-5f);
}
// weights: per-o mean|w| + sign bytes into swizzled planes g_wsp[tap][g][o&127][256B]
__global__ void k_prep_w(const float* __restrict__ wt) {
    int o = blockIdx.x, c = threadIdx.x;             // c = input channel (K pos within tap)
    const float* wo = wt + (size_t)o * KTOT + (size_t)c * 9;
    float v[9];
    float s = 0.f;
    #pragma unroll
    for (int t = 0; t < 9; t++) { v[t] = wo[t]; s += fabsf(v[t]); }
    __shared__ float sh[8];
    #pragma unroll
    for (int d = 16; d > 0; d >>= 1) s += __shfl_down_sync(0xffffffffu, s, d);
    if ((threadIdx.x & 31) == 0) sh[threadIdx.x >> 5] = s;
    __syncthreads();
    if (threadIdx.x == 0) {
        float t = 0.f;
        #pragma unroll
        for (int i = 0; i < 8; i++) t += sh[i];
        g_m[o] = t / (float)KTOT;
    }
    int g = o >> 7, ol = o & 127;
    int half = c >> 7, off = c & 127, seg = off >> 4, b = off & 15;
    int segp = (seg ^ (ol & 7));
    #pragma unroll
    for (int t = 0; t < 9; t++) {
        size_t pos = (((size_t)(t * 2 + g) * 128 + ol) * 256) + half * 128 + segp * 16 + b;
        g_wsp[pos] = (v[t] > 0.f) ? 1 : -1;
    }
}
__global__ void k_prep_x(const float* __restrict__ x) {
    int p = blockIdx.x * 256 + threadIdx.x;
    int cg = blockIdx.y;
    int n = p / HW, hw = p - n * HW;
    int h = hw / HDIM, w = hw - h * HDIM;
    const float* xp = x + ((size_t)(n * CIN + cg * 32)) * HW + hw;
    unsigned b[8];
    #pragma unroll
    for (int q = 0; q < 8; q++) {
        unsigned word = 0;
        #pragma unroll
        for (int j = 0; j < 4; j++) {
            float v = xp[(size_t)(q * 4 + j) * HW];
            word |= (v > 0.f ? 0x01u : 0xFFu) << (j * 8);
        }
        b[q] = word;
    }
    size_t row = (size_t)n * IMGP + (size_t)(h + 1) * HP + (w + 1) + GUARD;
    uint4* dst = (uint4*)(g_xs + row * 256 + cg * 32);
    dst[0] = make_uint4(b[0], b[1], b[2], b[3]);
    dst[1] = make_uint4(b[4], b[5], b[6], b[7]);
}
// zero guard + border rows of g_xs: 2*GUARD + 32*228 = 7440 rows x 16 segs
__global__ void k_zero_border() {
    int i = blockIdx.x * 256 + threadIdx.x;   // 465*256 = 119040
    int rowi = i >> 4, seg = i & 15;
    size_t row;
    if (rowi < 2 * GUARD) {
        row = (rowi < GUARD) ? (size_t)rowi : (size_t)(GUARD + NPAD + (rowi - GUARD));
    } else {
        int idx = rowi - 2 * GUARD;
        int n = idx / 228, j = idx - n * 228;
        int hp, wp;
        if (j < 58)       { hp = 0;  wp = j; }
        else if (j < 116) { hp = 57; wp = j - 58; }
        else if (j < 172) { wp = 0;  hp = j - 116 + 1; }
        else              { wp = 57; hp = j - 172 + 1; }
        row = (size_t)GUARD + (size_t)n * IMGP + hp * HP + wp;
    }
    ((uint4*)(g_xs + row * 256))[seg] = make_uint4(0, 0, 0, 0);
}
// build 3 dh-shifted, swizzled A planes: g_xp[dh][pr][seg16]
__global__ void k_planes() {
    int i = blockIdx.x * 256 + threadIdx.x;   // 3*PROWS*16 = 5,167,872 -> 20187 blocks
    int seg = i & 15;
    int r = i >> 4;
    int dh = r / PROWS;                        // 0..2
    int pr = r - dh * PROWS;                   // 0..PROWS-1
    int p  = pr - 8;                           // logical plane row
    size_t srow = (size_t)(GUARD + p + (dh - 1) * HP);
    uint4 v = *(const uint4*)(g_xs + srow * 256 + (size_t)seg * 16);
    int half = seg >> 3, s7 = seg & 7;
    int segp = half * 8 + (s7 ^ (pr & 7));     // pr&7 == p&7
    *(uint4*)(g_xp + ((size_t)dh * PROWS + pr) * 256 + (size_t)segp * 16) = v;
}

// ===================== int8 implicit-GEMM conv, bulk-copy pipeline =====================
// 512 thr / 16 warps (4x4), CTA M128 x N128, warp 32x32, 9 chunks of K=256, 3-stage ring.
__global__ void __launch_bounds__(512, 1) k_gemm(float* __restrict__ out) {
    extern __shared__ char smem[];
    const uint32_t sb = smem_u32(smem);
    __shared__ __align__(8) unsigned long long s_bar[6];   // full[s], empty[s]
    __shared__ float sm_m[128];
    const uint32_t barb = smem_u32(s_bar);

    const int tid = threadIdx.x;
    const int wid = tid >> 5;
    const int lane = tid & 31;
    const int warp_m = wid & 3;
    const int warp_n = wid >> 2;

    const int j0  = blockIdx.x * MT;
    const int gy  = blockIdx.y;                 // o-half
    const int ob0 = gy * 128;

    const int r16   = (lane & 7) + ((lane >> 3) & 1) * 8;
    const int khoff = ((lane >> 4) & 1) * 16;
    const int a_r0  = warp_m * 32 + r16;
    const int b_r0  = warp_n * 32 + r16;
    const int maskB = (lane & 7) * 16;

    if (tid == 0) {
        #pragma unroll
        for (int s = 0; s < STAGES; s++) {
            mbar_init(barb + s * 16, 1);        // full
            mbar_init(barb + s * 16 + 8, 16);   // empty
        }
    }
    if (tid < 128) sm_m[tid] = g_m[ob0 + tid];
    __syncthreads();

    // producer prologue: issue chunks 0..2
    if (tid == 0) {
        #pragma unroll
        for (int q = 0; q < 3; q++) {
            uint32_t full = barb + q * 16;
            mbar_expect_tx(full, STG);
            int dh = q / 3, dw = q % 3;         // q<3 -> dh=0
            const void* asrc = g_xp + ((size_t)dh * PROWS + 8 + j0 + dw - 1) * 256;
            bulkcp(sb + q * STG, asrc, CH_A, full);
            const void* bsrc = g_wsp + ((size_t)(q * 2 + gy)) * CH_B;
            bulkcp(sb + q * STG + CH_A, bsrc, CH_B, full);
        }
    }

    int acc[2][4][4];
    #pragma unroll
    for (int m = 0; m < 2; m++)
        #pragma unroll
        for (int g = 0; g < 4; g++)
            #pragma unroll
            for (int k = 0; k < 4; k++) acc[m][g][k] = 0;

    #pragma unroll 1
    for (int q = 0; q < NCHUNK; q++) {
        int s = q % 3;
        uint32_t kf = (uint32_t)((q / 3) & 1);
        mbar_wait(barb + s * 16, kf);           // wait full
        uint32_t sA = sb + s * STG;
        uint32_t sB = sA + CH_A;
        int dw = q % 3 - 1;
        int maskA = ((a_r0 + dw) & 7) * 16;
        #pragma unroll
        for (int ks = 0; ks < 8; ks++) {
            int half = (ks >> 2) * 128;
            int kh = (ks & 3) * 32 + khoff;
            int kxA = half + (kh ^ maskA);
            int kxB = half + (kh ^ maskB);
            uint32_t af[2][4], bf[2][4];
            ldsm4(af[0], sA + (unsigned)(a_r0 * 256) + kxA);
            ldsm4(af[1], sA + (unsigned)((a_r0 + 16) * 256) + kxA);
            ldsm4(bf[0], sB + (unsigned)(b_r0 * 256) + kxB);
            ldsm4(bf[1], sB + (unsigned)((b_r0 + 16) * 256) + kxB);
            #pragma unroll
            for (int i = 0; i < 2; i++) {
                imma(acc[0][i * 2 + 0], af[0], bf[i][0], bf[i][2]);
                imma(acc[1][i * 2 + 0], af[1], bf[i][0], bf[i][2]);
                imma(acc[0][i * 2 + 1], af[0], bf[i][1], bf[i][3]);
                imma(acc[1][i * 2 + 1], af[1], bf[i][1], bf[i][3]);
            }
        }
        if (lane == 0) mbar_arrive(barb + s * 16 + 8);   // arrive empty
        if (tid == 0 && q + 3 < NCHUNK) {
            int qq = q + 3;
            int k2 = qq / 3;
            uint32_t pe = (uint32_t)(1 - (k2 & 1));
            mbar_wait(barb + s * 16 + 8, pe);            // all 16 warps done with stage
            uint32_t full = barb + s * 16;
            mbar_expect_tx(full, STG);
            int dh = qq / 3, dw2 = qq % 3;
            const void* asrc = g_xp + ((size_t)dh * PROWS + 8 + j0 + dw2 - 1) * 256;
            bulkcp(sA, asrc, CH_A, full);
            const void* bsrc = g_wsp + ((size_t)(qq * 2 + gy)) * CH_B;
            bulkcp(sB, bsrc, CH_B, full);
        }
    }

    // -------- epilogue: transpose through smem, coalesced stores --------
    __syncthreads();
    float* sf = (float*)smem;                            // [128 oc][EPI_STRIDE]
    #pragma unroll
    for (int m = 0; m < 2; m++) {
        int row = warp_m * 32 + m * 16 + (lane >> 2);
        #pragma unroll
        for (int g = 0; g < 4; g++) {
            int col = warp_n * 32 + (g >> 1) * 16 + (g & 1) * 8 + (lane & 3) * 2;
            sf[(col    ) * EPI_STRIDE + row    ] = (float)acc[m][g][0];
            sf[(col + 1) * EPI_STRIDE + row    ] = (float)acc[m][g][1];
            sf[(col    ) * EPI_STRIDE + row + 8] = (float)acc[m][g][2];
            sf[(col + 1) * EPI_STRIDE + row + 8] = (float)acc[m][g][3];
        }
    }
    __syncthreads();

    int p_local = tid & 127, quarter = tid >> 7;
    int j = j0 + p_local;
    int n = j / IMGP, rem = j - n * IMGP;
    int hp = rem / HP, wp = rem - hp * HP;
    bool inter = (hp >= 1 && hp <= 56 && wp >= 1 && wp <= 56);
    float av = g_alpha[n];
    float* ob = out + ((size_t)n * OC + ob0) * HW + (hp - 1) * HDIM + (wp - 1);
    #pragma unroll 4
    for (int oo = 0; oo < 32; oo++) {
        int ol = quarter * 32 + oo;
        float v = sf[ol * EPI_STRIDE + p_local] * av * sm_m[ol];
        if (inter) ob[(size_t)ol * HW] = v;
    }
}

// ===================== launch =====================
extern "C" void kernel_launch(void* const* d_in, const int* in_sizes, int n_in,
                              void* d_out, int out_size) {
    const float* x  = (const float*)d_in[0];
    const float* wt = (const float*)d_in[1];
    float* out = (float*)d_out;

    k_absmean_x<<<NB * 16, 256>>>(x);
    k_alpha<<<1, 32>>>();
    k_prep_w<<<OC, 256>>>(wt);
    k_prep_x<<<dim3(PIXI / 256, 8), 256>>>(x);
    k_zero_border<<<465, 256>>>();
    k_planes<<<20187, 256>>>();

    static int smem_set = 0;
    if (!smem_set) {
        cudaFuncSetAttribute(k_gemm, cudaFuncAttributeMaxDynamicSharedMemorySize, SMEMG);
        smem_set = 1;
    }
    k_gemm<<<dim3(NTILES, 2), 512, SMEMG>>>(out);
}

// round 10
// speedup vs baseline: 1.9462x; 1.9462x over previous
#include <cuda_runtime.h>
#include <stdint.h>

#define NB     32
#define CIN    256
#define HDIM   56
#define HW     3136
#define PIXI   100352
#define OC     256
#define HP     58
#define IMGP   (HP*HP)          // 3364
#define NPAD   (NB*IMGP)        // 107648 = 841*128
#define GUARD  72
#define XROWS  (NPAD + 2*GUARD)
#define KTOT   2304
#define NTILES (NPAD/128)       // 841
#define PROWS  (NPAD + 16)
#define NCHUNK 9
#define OSP    192              // popcount covers o[0,192), IMMA o[192,256)
#define OCI    64               // imma oc count
#define CH_A   32768
#define CH_B   16384            // 64 oc * 256B
#define STG2   (CH_A + CH_B)    // 49152
#define WS_OFF  (3*STG2)            // 147456
#define WP_OFF  (WS_OFF + OSP*72*4) // 202752
#define SMM_OFF (WP_OFF + OSP*9*4)  // 209664
#define SMEMH   (SMM_OFF + 256*4)   // 210688
#define EPI_STRIDE 132

// ---- device scratch ----
__device__ float g_alpha[NB];
__device__ float g_m[OC];
__device__ float g_part[NB*16];
__device__ __align__(256) signed char g_xs[(size_t)XROWS*256];        // padded sign bytes
__device__ __align__(256) signed char g_xp[(size_t)3*PROWS*256];      // 3 dh-shifted swizzled A planes
__device__ __align__(256) signed char g_wsp2[(size_t)NCHUNK*OCI*256]; // imma B planes, o 192..255
__device__ unsigned g_xbits[(size_t)PIXI*8];                          // bit-packed x signs
__device__ unsigned g_wbits[OC*72];                                   // bit-packed w signs
__device__ int      g_wpop[OC*9];

// ===================== helpers =====================
__device__ __forceinline__ uint32_t smem_u32(const void* p) {
    uint32_t a;
    asm("{ .reg .u64 t; cvta.to.shared.u64 t, %1; cvt.u32.u64 %0, t; }" : "=r"(a) : "l"(p));
    return a;
}
__device__ __forceinline__ void mbar_init(uint32_t a, uint32_t cnt) {
    asm volatile("mbarrier.init.shared.b64 [%0], %1;" :: "r"(a), "r"(cnt) : "memory");
}
__device__ __forceinline__ void mbar_expect_tx(uint32_t a, uint32_t tx) {
    asm volatile("mbarrier.arrive.expect_tx.shared.b64 _, [%0], %1;" :: "r"(a), "r"(tx) : "memory");
}
__device__ __forceinline__ void mbar_arrive(uint32_t a) {
    asm volatile("mbarrier.arrive.shared.b64 _, [%0];" :: "r"(a) : "memory");
}
__device__ __forceinline__ void mbar_wait(uint32_t a, uint32_t ph) {
    asm volatile(
        "{ .reg .pred P;\n"
        "WL_%=: mbarrier.try_wait.parity.acquire.cta.shared::cta.b64 P, [%0], %1, 0x989680;\n"
        "@P bra WD_%=;\n"
        "bra WL_%=;\n"
        "WD_%=: }"
        :: "r"(a), "r"(ph) : "memory");
}
__device__ __forceinline__ void bulkcp(uint32_t dst, const void* src, uint32_t bytes, uint32_t mbar) {
    asm volatile("cp.async.bulk.shared::cluster.global.mbarrier::complete_tx::bytes [%0], [%1], %2, [%3];"
                 :: "r"(dst), "l"(src), "r"(bytes), "r"(mbar) : "memory");
}
__device__ __forceinline__ void ldsm4(uint32_t (&r)[4], uint32_t addr) {
    asm volatile("ldmatrix.sync.aligned.m8n8.x4.shared.b16 {%0,%1,%2,%3}, [%4];"
                 : "=r"(r[0]), "=r"(r[1]), "=r"(r[2]), "=r"(r[3]) : "r"(addr));
}
__device__ __forceinline__ void imma_op(int* c, const uint32_t* a, uint32_t b0, uint32_t b1) {
    asm volatile("mma.sync.aligned.m16n8k32.row.col.s32.s8.s8.s32 "
                 "{%0,%1,%2,%3}, {%4,%5,%6,%7}, {%8,%9}, {%0,%1,%2,%3};"
                 : "+r"(c[0]), "+r"(c[1]), "+r"(c[2]), "+r"(c[3])
                 : "r"(a[0]), "r"(a[1]), "r"(a[2]), "r"(a[3]), "r"(b0), "r"(b1));
}

// ===================== L0: |x| partial sums =====================
__global__ void k_absmean_x(const float* __restrict__ x) {
    int n = blockIdx.x >> 4;
    int chunk = blockIdx.x & 15;
    const float4* xv = (const float4*)x + (size_t)n * 200704 + (size_t)chunk * 12544;
    float s = 0.f;
    for (int i = threadIdx.x; i < 12544; i += 256) {
        float4 v = xv[i];
        s += fabsf(v.x) + fabsf(v.y) + fabsf(v.z) + fabsf(v.w);
    }
    __shared__ float sh[8];
    #pragma unroll
    for (int d = 16; d > 0; d >>= 1) s += __shfl_down_sync(0xffffffffu, s, d);
    if ((threadIdx.x & 31) == 0) sh[threadIdx.x >> 5] = s;
    __syncthreads();
    if (threadIdx.x == 0) {
        float t = 0.f;
        #pragma unroll
        for (int i = 0; i < 8; i++) t += sh[i];
        g_part[blockIdx.x] = t;
    }
}

// ===================== L1: mega prep (6993 blocks x 256) =====================
__global__ void k_megaprep(const float* __restrict__ x, const float* __restrict__ wt) {
    int bid = blockIdx.x;
    int tid = threadIdx.x;
    if (bid < 256) {
        // ---- weights: mean|w|, bit-pack, per-tap popc, imma B planes ----
        int o = bid, c = tid;
        const float* wo = wt + (size_t)o * KTOT;
        const float* woc = wo + (size_t)c * 9;
        float v[9];
        float s = 0.f;
        #pragma unroll
        for (int t = 0; t < 9; t++) { v[t] = woc[t]; s += fabsf(v[t]); }
        __shared__ float sh[8];
        __shared__ unsigned pw[72];
        #pragma unroll
        for (int d = 16; d > 0; d >>= 1) s += __shfl_down_sync(0xffffffffu, s, d);
        if ((tid & 31) == 0) sh[tid >> 5] = s;
        __syncthreads();
        if (tid == 0) {
            float t = 0.f;
            #pragma unroll
            for (int i = 0; i < 8; i++) t += sh[i];
            g_m[o] = t / (float)KTOT;
        }
        if (tid < 72) {
            int t = tid / 8, cc = tid % 8;
            unsigned word = 0u;
            #pragma unroll
            for (int j = 0; j < 32; j++)
                if (wo[(cc * 32 + j) * 9 + t] > 0.f) word |= (1u << j);
            g_wbits[o * 72 + t * 8 + cc] = word;
            pw[t * 8 + cc] = (unsigned)__popc(word);
        }
        __syncthreads();
        if (tid < 9) {
            int acc = 0;
            #pragma unroll
            for (int cc = 0; cc < 8; cc++) acc += (int)pw[tid * 8 + cc];
            g_wpop[o * 9 + tid] = acc;
        }
        if (o >= 192) {
            int ol = o - 192;
            int half = c >> 7, off = c & 127, seg = off >> 4, bb = off & 15;
            int segp = seg ^ (ol & 7);
            #pragma unroll
            for (int t = 0; t < 9; t++)
                g_wsp2[((size_t)(t * OCI + ol) * 256) + half * 128 + segp * 16 + bb] =
                    (v[t] > 0.f) ? 1 : -1;
        }
    } else if (bid < 3392) {
        // ---- x sign bytes -> padded g_xs ----
        int b = bid - 256;
        int bx = b % 392, cg = b / 392;
        int p = bx * 256 + tid;
        int n = p / HW, hw = p - n * HW;
        int h = hw / HDIM, w = hw - h * HDIM;
        const float* xp = x + ((size_t)(n * CIN + cg * 32)) * HW + hw;
        unsigned bb[8];
        #pragma unroll
        for (int q = 0; q < 8; q++) {
            unsigned word = 0;
            #pragma unroll
            for (int j = 0; j < 4; j++) {
                float v = xp[(size_t)(q * 4 + j) * HW];
                word |= (v > 0.f ? 0x01u : 0xFFu) << (j * 8);
            }
            bb[q] = word;
        }
        size_t row = (size_t)n * IMGP + (size_t)(h + 1) * HP + (w + 1) + GUARD;
        uint4* dst = (uint4*)(g_xs + row * 256 + cg * 32);
        dst[0] = make_uint4(bb[0], bb[1], bb[2], bb[3]);
        dst[1] = make_uint4(bb[4], bb[5], bb[6], bb[7]);
    } else if (bid < 6528) {
        // ---- x bit-pack -> g_xbits ----
        int b = bid - 3392;
        int bx = b % 392, cg = b / 392;
        int p = bx * 256 + tid;
        int n = p / HW, hw = p - n * HW;
        const float* xp = x + ((size_t)(n * CIN + cg * 32)) * HW + hw;
        unsigned word = 0u;
        #pragma unroll
        for (int j = 0; j < 32; j++)
            if (xp[(size_t)j * HW] > 0.f) word |= (1u << j);
        g_xbits[(size_t)p * 8 + cg] = word;
    } else {
        // ---- zero guard + border rows of g_xs ----
        int i = (bid - 6528) * 256 + tid;       // 465*256 = 119040 = 7440 rows * 16
        int rowi = i >> 4, seg = i & 15;
        size_t row;
        if (rowi < 2 * GUARD) {
            row = (rowi < GUARD) ? (size_t)rowi : (size_t)(GUARD + NPAD + (rowi - GUARD));
        } else {
            int idx = rowi - 2 * GUARD;
            int n = idx / 228, j = idx - n * 228;
            int hp, wp;
            if (j < 58)       { hp = 0;  wp = j; }
            else if (j < 116) { hp = 57; wp = j - 58; }
            else if (j < 172) { wp = 0;  hp = j - 116 + 1; }
            else              { wp = 57; hp = j - 172 + 1; }
            row = (size_t)GUARD + (size_t)n * IMGP + hp * HP + wp;
        }
        ((uint4*)(g_xs + row * 256))[seg] = make_uint4(0, 0, 0, 0);
    }
}

// ===================== L2: alpha + A planes (20188 blocks) =====================
__global__ void k_alpha_planes() {
    if (blockIdx.x == 0) {
        if (threadIdx.x < 32) {
            int n = threadIdx.x;
            float s = 0.f;
            #pragma unroll
            for (int i = 0; i < 16; i++) s += g_part[n * 16 + i];
            float a = 2.f * s / (float)(CIN * HW);
            g_alpha[n] = fmaxf(a, 1e-5f);
        }
        return;
    }
    int i = (blockIdx.x - 1) * 256 + threadIdx.x;     // < 3*PROWS*16
    int seg = i & 15;
    int r = i >> 4;
    int dh = r / PROWS;
    int pr = r - dh * PROWS;
    int p  = pr - 8;
    size_t srow = (size_t)(GUARD + p + (dh - 1) * HP);
    uint4 v = *(const uint4*)(g_xs + srow * 256 + (size_t)seg * 16);
    int half = seg >> 3, s7 = seg & 7;
    int segp = half * 8 + (s7 ^ (pr & 7));
    *(uint4*)(g_xp + ((size_t)dh * PROWS + pr) * 256 + (size_t)segp * 16) = v;
}

// ===================== L3: hybrid conv (imma o[192,256) + popcount o[0,192)) ====
__global__ void __launch_bounds__(512, 1) k_hybrid(float* __restrict__ out) {
    extern __shared__ char smem[];
    const uint32_t sb = smem_u32(smem);
    __shared__ __align__(8) unsigned long long s_bar[6];
    const uint32_t barb = smem_u32(s_bar);

    const int tid = threadIdx.x;
    const int wid = tid >> 5;
    const int lane = tid & 31;
    const int j0 = blockIdx.x * 128;

    unsigned* ws = (unsigned*)(smem + WS_OFF);
    int* wps = (int*)(smem + WP_OFF);
    float* smm = (float*)(smem + SMM_OFF);

    if (tid == 0) {
        #pragma unroll
        for (int s = 0; s < 3; s++) {
            mbar_init(barb + s * 16, 1);       // full (tx-based)
            mbar_init(barb + s * 16 + 8, 8);   // empty: 8 imma warps
        }
    }
    for (int i = tid; i < OSP * 72; i += 512) ws[i] = g_wbits[i];
    for (int i = tid; i < OSP * 9; i += 512) wps[i] = g_wpop[i];
    if (tid < 256) smm[tid] = g_m[tid];
    __syncthreads();

    if (tid == 0) {
        #pragma unroll
        for (int q = 0; q < 3; q++) {
            uint32_t full = barb + q * 16;
            mbar_expect_tx(full, STG2);
            bulkcp(sb + q * STG2, g_xp + ((size_t)(8 + j0 + (q % 3) - 1)) * 256, CH_A, full);
            bulkcp(sb + q * STG2 + CH_A, g_wsp2 + (size_t)q * CH_B, CH_B, full);
        }
    }

    if (tid < 256) {
        // ================= IMMA half: o in [192, 256) =================
        const int warp_m = wid & 3;
        const int warp_n = wid >> 2;           // 0..1
        const int r16   = (lane & 7) + ((lane >> 3) & 1) * 8;
        const int khoff = ((lane >> 4) & 1) * 16;
        const int a_r0  = warp_m * 32 + r16;
        const int b_r0  = warp_n * 32 + r16;
        const int maskB = (lane & 7) * 16;

        int acc[2][4][4];
        #pragma unroll
        for (int m = 0; m < 2; m++)
            #pragma unroll
            for (int g = 0; g < 4; g++)
                #pragma unroll
                for (int k = 0; k < 4; k++) acc[m][g][k] = 0;

        #pragma unroll 1
        for (int q = 0; q < NCHUNK; q++) {
            int s = q % 3;
            mbar_wait(barb + s * 16, (uint32_t)((q / 3) & 1));
            uint32_t sA = sb + s * STG2;
            uint32_t sB = sA + CH_A;
            int dw = q % 3 - 1;
            int maskA = ((a_r0 + dw) & 7) * 16;
            #pragma unroll
            for (int ks = 0; ks < 8; ks++) {
                int half = (ks >> 2) * 128;
                int kh = (ks & 3) * 32 + khoff;
                int kxA = half + (kh ^ maskA);
                int kxB = half + (kh ^ maskB);
                uint32_t af[2][4], bf[2][4];
                ldsm4(af[0], sA + (unsigned)(a_r0 * 256) + kxA);
                ldsm4(af[1], sA + (unsigned)((a_r0 + 16) * 256) + kxA);
                ldsm4(bf[0], sB + (unsigned)(b_r0 * 256) + kxB);
                ldsm4(bf[1], sB + (unsigned)((b_r0 + 16) * 256) + kxB);
                #pragma unroll
                for (int i = 0; i < 2; i++) {
                    imma_op(acc[0][i * 2 + 0], af[0], bf[i][0], bf[i][2]);
                    imma_op(acc[1][i * 2 + 0], af[1], bf[i][0], bf[i][2]);
                    imma_op(acc[0][i * 2 + 1], af[0], bf[i][1], bf[i][3]);
                    imma_op(acc[1][i * 2 + 1], af[1], bf[i][1], bf[i][3]);
                }
            }
            if (lane == 0) mbar_arrive(barb + s * 16 + 8);
            if (tid == 0 && q + 3 < NCHUNK) {
                int qq = q + 3;
                mbar_wait(barb + s * 16 + 8, (uint32_t)(1 - ((qq / 3) & 1)));
                uint32_t full = barb + s * 16;
                mbar_expect_tx(full, STG2);
                int dh = qq / 3, dw2 = qq % 3;
                bulkcp(sA, g_xp + ((size_t)dh * PROWS + 8 + j0 + dw2 - 1) * 256, CH_A, full);
                bulkcp(sB, g_wsp2 + (size_t)qq * CH_B, CH_B, full);
            }
        }

        // epilogue: transpose through stage-0 smem (imma-private), coalesced stores
        asm volatile("bar.sync 2, 256;" ::: "memory");
        float* sf = (float*)smem;                       // [64 oc][EPI_STRIDE]
        #pragma unroll
        for (int m = 0; m < 2; m++) {
            int row = warp_m * 32 + m * 16 + (lane >> 2);
            #pragma unroll
            for (int g = 0; g < 4; g++) {
                int col = warp_n * 32 + (g >> 1) * 16 + (g & 1) * 8 + (lane & 3) * 2;
                sf[(col    ) * EPI_STRIDE + row    ] = (float)acc[m][g][0];
                sf[(col + 1) * EPI_STRIDE + row    ] = (float)acc[m][g][1];
                sf[(col    ) * EPI_STRIDE + row + 8] = (float)acc[m][g][2];
                sf[(col + 1) * EPI_STRIDE + row + 8] = (float)acc[m][g][3];
            }
        }
        asm volatile("bar.sync 2, 256;" ::: "memory");

        int p_local = tid & 127, halfq = tid >> 7;      // 2 halves x 32 oc
        int j = j0 + p_local;
        int n = j / IMGP, rem = j - n * IMGP;
        int hp = rem / HP, wq = rem - hp * HP;
        bool inter = (hp >= 1 && hp <= 56 && wq >= 1 && wq <= 56);
        float av = g_alpha[n];
        float* ob = out + ((size_t)n * OC + 192) * HW + (hp - 1) * HDIM + (wq - 1);
        #pragma unroll 4
        for (int oo = 0; oo < 32; oo++) {
            int ol = halfq * 32 + oo;
            float v = sf[ol * EPI_STRIDE + p_local] * av * smm[192 + ol];
            if (inter) ob[(size_t)ol * HW] = v;
        }
    } else {
        // ================= popcount half: o in [0, 192) =================
        int t = tid - 256;
        int px = t & 127;
        int og = t >> 7;                               // 0/1 -> o 0..95 / 96..191
        int j = j0 + px;
        int n = j / IMGP, rem = j - n * IMGP;
        int hp = rem / HP, wq = rem - hp * HP;
        if (hp >= 1 && hp <= 56 && wq >= 1 && wq <= 56) {
            int h = hp - 1, w = wq - 1;
            unsigned xb[72];
            unsigned invmask = 0u;
            #pragma unroll
            for (int tp = 0; tp < 9; tp++) {
                int hh = h + tp / 3 - 1;
                int ww = w + tp % 3 - 1;
                if (hh >= 0 && hh < HDIM && ww >= 0 && ww < HDIM) {
                    const uint4* src = (const uint4*)&g_xbits[((size_t)(n * HW + hh * HDIM + ww)) * 8];
                    uint4 a = src[0], b = src[1];
                    xb[tp*8+0]=a.x; xb[tp*8+1]=a.y; xb[tp*8+2]=a.z; xb[tp*8+3]=a.w;
                    xb[tp*8+4]=b.x; xb[tp*8+5]=b.y; xb[tp*8+6]=b.z; xb[tp*8+7]=b.w;
                } else {
                    invmask |= (1u << tp);
                    #pragma unroll
                    for (int cc = 0; cc < 8; cc++) xb[tp*8+cc] = 0u;
                }
            }
            float av = g_alpha[n];
            float* op = out + ((size_t)n * OC) * HW + h * HDIM + w;
            int o_end = og * 96 + 96;
            for (int o = og * 96; o < o_end; o++) {
                const uint4* wr = (const uint4*)&ws[o * 72];
                int acc = 0;
                #pragma unroll
                for (int q = 0; q < 18; q++) {
                    uint4 v = wr[q];
                    acc += __popc(xb[q*4+0] ^ v.x) + __popc(xb[q*4+1] ^ v.y)
                         + __popc(xb[q*4+2] ^ v.z) + __popc(xb[q*4+3] ^ v.w);
                }
                int dot = KTOT - 2 * acc;
                if (invmask) {
                    unsigned mm = invmask;
                    while (mm) {
                        int tp = __ffs(mm) - 1; mm &= mm - 1;
                        dot -= (256 - 2 * wps[o * 9 + tp]);
                    }
                }
                op[(size_t)o * HW] = av * smm[o] * (float)dot;
            }
        }
    }
}

// ===================== launch =====================
extern "C" void kernel_launch(void* const* d_in, const int* in_sizes, int n_in,
                              void* d_out, int out_size) {
    const float* x  = (const float*)d_in[0];
    const float* wt = (const float*)d_in[1];
    float* out = (float*)d_out;

    k_absmean_x<<<NB * 16, 256>>>(x);
    k_megaprep<<<6993, 256>>>(x, wt);
    k_alpha_planes<<<20188, 256>>>();

    static int smem_set = 0;
    if (!smem_set) {
        cudaFuncSetAttribute(k_hybrid, cudaFuncAttributeMaxDynamicSharedMemorySize, SMEMH);
        smem_set = 1;
    }
    k_hybrid<<<NTILES, 512, SMEMH>>>(out);
}

// round 12
// speedup vs baseline: 2.1660x; 1.1130x over previous
#include <cuda_runtime.h>
#include <stdint.h>

#define NB     32
#define CIN    256
#define HDIM   56
#define HW     3136
#define PIXI   100352
#define OC     256
#define HP     58
#define IMGP   (HP*HP)          // 3364
#define NPAD   (NB*IMGP)        // 107648 = 841*128
#define GUARD  72
#define XROWS  (NPAD + 2*GUARD)
#define KTOT   2304
#define NTILES (NPAD/128)       // 841
#define NCHUNK 9
#define OSP    160              // popcount covers o[0,160)
#define OCI    96               // imma covers o[160,256)
#define CH_A   32768            // 128 rows * 256B
#define CH_B   (OCI*256)        // 24576
#define STG2   (CH_A + CH_B)    // 57344
#define WS_OFF  (3*STG2)                // 172032
#define WP_OFF  (WS_OFF + OSP*72*4)     // 218112
#define SMM_OFF (WP_OFF + OSP*9*4)      // 223872
#define SMEMH   (SMM_OFF + 256*4)       // 224896
#define EPI_STRIDE 132

// ---- device scratch ----
__device__ float g_alpha[NB];
__device__ float g_m[OC];
__device__ float g_part[NB*16];
__device__ __align__(256) signed char g_xs[(size_t)XROWS*256];        // padded sign bytes, PRE-SWIZZLED
__device__ __align__(256) signed char g_wsp2[(size_t)NCHUNK*OCI*256]; // imma B planes, o 160..255
__device__ unsigned g_xbits[(size_t)PIXI*8];                          // bit-packed x signs
__device__ unsigned g_wbits[OC*72];                                   // bit-packed w signs
__device__ int      g_wpop[OC*9];

// ===================== helpers =====================
__device__ __forceinline__ uint32_t smem_u32(const void* p) {
    uint32_t a;
    asm("{ .reg .u64 t; cvta.to.shared.u64 t, %1; cvt.u32.u64 %0, t; }" : "=r"(a) : "l"(p));
    return a;
}
__device__ __forceinline__ void mbar_init(uint32_t a, uint32_t cnt) {
    asm volatile("mbarrier.init.shared.b64 [%0], %1;" :: "r"(a), "r"(cnt) : "memory");
}
__device__ __forceinline__ void mbar_expect_tx(uint32_t a, uint32_t tx) {
    asm volatile("mbarrier.arrive.expect_tx.shared.b64 _, [%0], %1;" :: "r"(a), "r"(tx) : "memory");
}
__device__ __forceinline__ void mbar_arrive(uint32_t a) {
    asm volatile("mbarrier.arrive.shared.b64 _, [%0];" :: "r"(a) : "memory");
}
__device__ __forceinline__ void mbar_wait(uint32_t a, uint32_t ph) {
    asm volatile(
        "{ .reg .pred P;\n"
        "WL_%=: mbarrier.try_wait.parity.acquire.cta.shared::cta.b64 P, [%0], %1, 0x989680;\n"
        "@P bra WD_%=;\n"
        "bra WL_%=;\n"
        "WD_%=: }"
        :: "r"(a), "r"(ph) : "memory");
}
__device__ __forceinline__ void bulkcp(uint32_t dst, const void* src, uint32_t bytes, uint32_t mbar) {
    asm volatile("cp.async.bulk.shared::cluster.global.mbarrier::complete_tx::bytes [%0], [%1], %2, [%3];"
                 :: "r"(dst), "l"(src), "r"(bytes), "r"(mbar) : "memory");
}
__device__ __forceinline__ void ldsm4(uint32_t (&r)[4], uint32_t addr) {
    asm volatile("ldmatrix.sync.aligned.m8n8.x4.shared.b16 {%0,%1,%2,%3}, [%4];"
                 : "=r"(r[0]), "=r"(r[1]), "=r"(r[2]), "=r"(r[3]) : "r"(addr));
}
__device__ __forceinline__ void imma_op(int* c, const uint32_t* a, uint32_t b0, uint32_t b1) {
    asm volatile("mma.sync.aligned.m16n8k32.row.col.s32.s8.s8.s32 "
                 "{%0,%1,%2,%3}, {%4,%5,%6,%7}, {%8,%9}, {%0,%1,%2,%3};"
                 : "+r"(c[0]), "+r"(c[1]), "+r"(c[2]), "+r"(c[3])
                 : "r"(a[0]), "r"(a[1]), "r"(a[2]), "r"(a[3]), "r"(b0), "r"(b1));
}

// ===================== L0: |x| partial sums =====================
__global__ void k_absmean_x(const float* __restrict__ x) {
    int n = blockIdx.x >> 4;
    int chunk = blockIdx.x & 15;
    const float4* xv = (const float4*)x + (size_t)n * 200704 + (size_t)chunk * 12544;
    float s = 0.f;
    for (int i = threadIdx.x; i < 12544; i += 256) {
        float4 v = xv[i];
        s += fabsf(v.x) + fabsf(v.y) + fabsf(v.z) + fabsf(v.w);
    }
    __shared__ float sh[8];
    #pragma unroll
    for (int d = 16; d > 0; d >>= 1) s += __shfl_down_sync(0xffffffffu, s, d);
    if ((threadIdx.x & 31) == 0) sh[threadIdx.x >> 5] = s;
    __syncthreads();
    if (threadIdx.x == 0) {
        float t = 0.f;
        #pragma unroll
        for (int i = 0; i < 8; i++) t += sh[i];
        g_part[blockIdx.x] = t;
    }
}

// ===================== L1: mega prep (6994 blocks x 256) =====================
__global__ void k_megaprep(const float* __restrict__ x, const float* __restrict__ wt) {
    int bid = blockIdx.x;
    int tid = threadIdx.x;
    if (bid < 256) {
        // ---- weights: mean|w|, bit-pack, per-tap popc, imma B planes ----
        int o = bid, c = tid;
        const float* wo = wt + (size_t)o * KTOT;
        const float* woc = wo + (size_t)c * 9;
        float v[9];
        float s = 0.f;
        #pragma unroll
        for (int t = 0; t < 9; t++) { v[t] = woc[t]; s += fabsf(v[t]); }
        __shared__ float sh[8];
        __shared__ unsigned pw[72];
        #pragma unroll
        for (int d = 16; d > 0; d >>= 1) s += __shfl_down_sync(0xffffffffu, s, d);
        if ((tid & 31) == 0) sh[tid >> 5] = s;
        __syncthreads();
        if (tid == 0) {
            float t = 0.f;
            #pragma unroll
            for (int i = 0; i < 8; i++) t += sh[i];
            g_m[o] = t / (float)KTOT;
        }
        if (tid < 72) {
            int t = tid / 8, cc = tid % 8;
            unsigned word = 0u;
            #pragma unroll
            for (int j = 0; j < 32; j++)
                if (wo[(cc * 32 + j) * 9 + t] > 0.f) word |= (1u << j);
            g_wbits[o * 72 + t * 8 + cc] = word;
            pw[t * 8 + cc] = (unsigned)__popc(word);
        }
        __syncthreads();
        if (tid < 9) {
            int acc = 0;
            #pragma unroll
            for (int cc = 0; cc < 8; cc++) acc += (int)pw[tid * 8 + cc];
            g_wpop[o * 9 + tid] = acc;
        }
        if (o >= 160) {
            int ol = o - 160;
            int half = c >> 7, off = c & 127, seg = off >> 4, bb = off & 15;
            int segp = seg ^ (ol & 7);
            #pragma unroll
            for (int t = 0; t < 9; t++)
                g_wsp2[((size_t)(t * OCI + ol) * 256) + half * 128 + segp * 16 + bb] =
                    (v[t] > 0.f) ? 1 : -1;
        }
    } else if (bid < 3392) {
        // ---- x sign bytes -> padded, PRE-SWIZZLED g_xs ----
        int b = bid - 256;
        int bx = b % 392, cg = b / 392;
        int p = bx * 256 + tid;
        int n = p / HW, hw = p - n * HW;
        int h = hw / HDIM, w = hw - h * HDIM;
        const float* xp = x + ((size_t)(n * CIN + cg * 32)) * HW + hw;
        unsigned bb[8];
        #pragma unroll
        for (int q = 0; q < 8; q++) {
            unsigned word = 0;
            #pragma unroll
            for (int j = 0; j < 4; j++) {
                float v = xp[(size_t)(q * 4 + j) * HW];
                word |= (v > 0.f ? 0x01u : 0xFFu) << (j * 8);
            }
            bb[q] = word;
        }
        size_t row = (size_t)n * IMGP + (size_t)(h + 1) * HP + (w + 1) + GUARD;
        int rb = (int)(row & 7);
        int s0 = cg * 2;
        *(uint4*)(g_xs + row * 256 + (size_t)((s0    ) ^ rb) * 16) = make_uint4(bb[0], bb[1], bb[2], bb[3]);
        *(uint4*)(g_xs + row * 256 + (size_t)((s0 + 1) ^ rb) * 16) = make_uint4(bb[4], bb[5], bb[6], bb[7]);
    } else if (bid < 6528) {
        // ---- x bit-pack -> g_xbits ----
        int b = bid - 3392;
        int bx = b % 392, cg = b / 392;
        int p = bx * 256 + tid;
        int n = p / HW, hw = p - n * HW;
        const float* xp = x + ((size_t)(n * CIN + cg * 32)) * HW + hw;
        unsigned word = 0u;
        #pragma unroll
        for (int j = 0; j < 32; j++)
            if (xp[(size_t)j * HW] > 0.f) word |= (1u << j);
        g_xbits[(size_t)p * 8 + cg] = word;
    } else if (bid < 6993) {
        // ---- zero guard + border rows (swizzle-invariant) ----
        int i = (bid - 6528) * 256 + tid;       // 465*256 = 7440 rows * 16
        int rowi = i >> 4, seg = i & 15;
        size_t row;
        if (rowi < 2 * GUARD) {
            row = (rowi < GUARD) ? (size_t)rowi : (size_t)(GUARD + NPAD + (rowi - GUARD));
        } else {
            int idx = rowi - 2 * GUARD;
            int n = idx / 228, j = idx - n * 228;
            int hp, wp;
            if (j < 58)       { hp = 0;  wp = j; }
            else if (j < 116) { hp = 57; wp = j - 58; }
            else if (j < 172) { wp = 0;  hp = j - 116 + 1; }
            else              { wp = 57; hp = j - 172 + 1; }
            row = (size_t)GUARD + (size_t)n * IMGP + hp * HP + wp;
        }
        ((uint4*)(g_xs + row * 256))[seg] = make_uint4(0, 0, 0, 0);
    } else {
        // ---- alpha ----
        if (tid < 32) {
            int n = tid;
            float s = 0.f;
            #pragma unroll
            for (int i = 0; i < 16; i++) s += g_part[n * 16 + i];
            float a = 2.f * s / (float)(CIN * HW);
            g_alpha[n] = fmaxf(a, 1e-5f);
        }
    }
}

// ===================== L2: hybrid conv (imma o[160,256) + popcount o[0,160)) ====
__global__ void __launch_bounds__(512, 1) k_hybrid(float* __restrict__ out) {
    extern __shared__ char smem[];
    const uint32_t sb = smem_u32(smem);
    __shared__ __align__(8) unsigned long long s_bar[6];
    const uint32_t barb = smem_u32(s_bar);

    const int tid = threadIdx.x;
    const int wid = tid >> 5;
    const int lane = tid & 31;
    const int j0 = blockIdx.x * 128;

    unsigned* ws = (unsigned*)(smem + WS_OFF);
    int* wps = (int*)(smem + WP_OFF);
    float* smm = (float*)(smem + SMM_OFF);

    if (tid == 0) {
        #pragma unroll
        for (int s = 0; s < 3; s++) {
            mbar_init(barb + s * 16, 1);       // full (tx-based)
            mbar_init(barb + s * 16 + 8, 8);   // empty: 8 imma warps
        }
    }
    for (int i = tid; i < OSP * 72; i += 512) ws[i] = g_wbits[i];
    for (int i = tid; i < OSP * 9; i += 512) wps[i] = g_wpop[i];
    if (tid < 256) smm[tid] = g_m[tid];
    __syncthreads();

    if (tid == 0) {
        #pragma unroll
        for (int q = 0; q < 3; q++) {
            uint32_t full = barb + q * 16;
            mbar_expect_tx(full, STG2);
            int od = (q / 3 - 1) * HP + (q % 3 - 1);       // q<3: dh=0
            bulkcp(sb + q * STG2, g_xs + ((size_t)(GUARD + j0 + od)) * 256, CH_A, full);
            bulkcp(sb + q * STG2 + CH_A, g_wsp2 + (size_t)q * CH_B, CH_B, full);
        }
    }

    if (tid < 256) {
        // ================= IMMA half: o in [160, 256), warp tile 32x48 ==========
        const int warp_m = wid & 3;
        const int warp_n = wid >> 2;           // 0..1
        const int r16   = (lane & 7) + ((lane >> 3) & 1) * 8;
        const int khoff = ((lane >> 4) & 1) * 16;
        const int a_r0  = warp_m * 32 + r16;
        const int b_r0  = warp_n * 48 + r16;
        const int maskB = (lane & 7) * 16;

        int acc[2][6][4];
        #pragma unroll
        for (int m = 0; m < 2; m++)
            #pragma unroll
            for (int g = 0; g < 6; g++)
                #pragma unroll
                for (int k = 0; k < 4; k++) acc[m][g][k] = 0;

        #pragma unroll 1
        for (int q = 0; q < NCHUNK; q++) {
            int s = q % 3;
            mbar_wait(barb + s * 16, (uint32_t)((q / 3) & 1));
            uint32_t sA = sb + s * STG2;
            uint32_t sB = sA + CH_A;
            int od = (q / 3 - 1) * HP + (q % 3 - 1);
            int maskA = ((od + a_r0) & 7) * 16;
            #pragma unroll
            for (int ks = 0; ks < 8; ks++) {
                int half = (ks >> 2) * 128;
                int kh = (ks & 3) * 32 + khoff;
                int kxA = half + (kh ^ maskA);
                int kxB = half + (kh ^ maskB);
                uint32_t af[2][4], bf[3][4];
                ldsm4(af[0], sA + (unsigned)(a_r0 * 256) + kxA);
                ldsm4(af[1], sA + (unsigned)((a_r0 + 16) * 256) + kxA);
                ldsm4(bf[0], sB + (unsigned)(b_r0 * 256) + kxB);
                ldsm4(bf[1], sB + (unsigned)((b_r0 + 16) * 256) + kxB);
                ldsm4(bf[2], sB + (unsigned)((b_r0 + 32) * 256) + kxB);
                #pragma unroll
                for (int i = 0; i < 3; i++) {
                    imma_op(acc[0][i * 2 + 0], af[0], bf[i][0], bf[i][2]);
                    imma_op(acc[1][i * 2 + 0], af[1], bf[i][0], bf[i][2]);
                    imma_op(acc[0][i * 2 + 1], af[0], bf[i][1], bf[i][3]);
                    imma_op(acc[1][i * 2 + 1], af[1], bf[i][1], bf[i][3]);
                }
            }
            if (lane == 0) mbar_arrive(barb + s * 16 + 8);
            if (tid == 0 && q + 3 < NCHUNK) {
                int qq = q + 3;
                mbar_wait(barb + s * 16 + 8, (uint32_t)(1 - ((qq / 3) & 1)));
                uint32_t full = barb + s * 16;
                mbar_expect_tx(full, STG2);
                int od2 = (qq / 3 - 1) * HP + (qq % 3 - 1);
                bulkcp(sA, g_xs + ((size_t)(GUARD + j0 + od2)) * 256, CH_A, full);
                bulkcp(sB, g_wsp2 + (size_t)qq * CH_B, CH_B, full);
            }
        }

        // epilogue: transpose through low smem (disjoint from ws region)
        asm volatile("bar.sync 2, 256;" ::: "memory");
        float* sf = (float*)smem;                       // [96 oc][EPI_STRIDE]
        #pragma unroll
        for (int m = 0; m < 2; m++) {
            int row = warp_m * 32 + m * 16 + (lane >> 2);
            #pragma unroll
            for (int g = 0; g < 6; g++) {
                int col = warp_n * 48 + (g >> 1) * 16 + (g & 1) * 8 + (lane & 3) * 2;
                sf[(col    ) * EPI_STRIDE + row    ] = (float)acc[m][g][0];
                sf[(col + 1) * EPI_STRIDE + row    ] = (float)acc[m][g][1];
                sf[(col    ) * EPI_STRIDE + row + 8] = (float)acc[m][g][2];
                sf[(col + 1) * EPI_STRIDE + row + 8] = (float)acc[m][g][3];
            }
        }
        asm volatile("bar.sync 2, 256;" ::: "memory");

        int p_local = tid & 127, halfq = tid >> 7;      // 2 halves x 48 oc
        int j = j0 + p_local;
        int n = j / IMGP, rem = j - n * IMGP;
        int hp = rem / HP, wq = rem - hp * HP;
        bool inter = (hp >= 1 && hp <= 56 && wq >= 1 && wq <= 56);
        float av = g_alpha[n];
        float* ob = out + ((size_t)n * OC + 160) * HW + (hp - 1) * HDIM + (wq - 1);
        #pragma unroll 4
        for (int oo = 0; oo < 48; oo++) {
            int ol = halfq * 48 + oo;
            float v = sf[ol * EPI_STRIDE + p_local] * av * smm[160 + ol];
            if (inter) ob[(size_t)ol * HW] = v;
        }
    } else {
        // ================= popcount half: o in [0, 160) =================
        int t = tid - 256;
        int px = t & 127;
        int og = t >> 7;                               // 0/1 -> o 0..79 / 80..159
        int j = j0 + px;
        int n = j / IMGP, rem = j - n * IMGP;
        int hp = rem / HP, wq = rem - hp * HP;
        if (hp >= 1 && hp <= 56 && wq >= 1 && wq <= 56) {
            int h = hp - 1, w = wq - 1;
            unsigned xb[72];
            unsigned invmask = 0u;
            #pragma unroll
            for (int tp = 0; tp < 9; tp++) {
                int hh = h + tp / 3 - 1;
                int ww = w + tp % 3 - 1;
                if (hh >= 0 && hh < HDIM && ww >= 0 && ww < HDIM) {
                    const uint4* src = (const uint4*)&g_xbits[((size_t)(n * HW + hh * HDIM + ww)) * 8];
                    uint4 a = src[0], b = src[1];
                    xb[tp*8+0]=a.x; xb[tp*8+1]=a.y; xb[tp*8+2]=a.z; xb[tp*8+3]=a.w;
                    xb[tp*8+4]=b.x; xb[tp*8+5]=b.y; xb[tp*8+6]=b.z; xb[tp*8+7]=b.w;
                } else {
                    invmask |= (1u << tp);
                    #pragma unroll
                    for (int cc = 0; cc < 8; cc++) xb[tp*8+cc] = 0u;
                }
            }
            float av = g_alpha[n];
            float* op = out + ((size_t)n * OC) * HW + h * HDIM + w;
            int o_end = og * 80 + 80;
            for (int o = og * 80; o < o_end; o++) {
                const uint4* wr = (const uint4*)&ws[o * 72];
                int acc = 0;
                #pragma unroll
                for (int q = 0; q < 18; q++) {
                    uint4 v = wr[q];
                    acc += __popc(xb[q*4+0] ^ v.x) + __popc(xb[q*4+1] ^ v.y)
                         + __popc(xb[q*4+2] ^ v.z) + __popc(xb[q*4+3] ^ v.w);
                }
                int dot = KTOT - 2 * acc;
                if (invmask) {
                    unsigned mm = invmask;
                    while (mm) {
                        int tp = __ffs(mm) - 1; mm &= mm - 1;
                        dot -= (256 - 2 * wps[o * 9 + tp]);
                    }
                }
                op[(size_t)o * HW] = av * smm[o] * (float)dot;
            }
        }
    }
}

// ===================== launch =====================
extern "C" void kernel_launch(void* const* d_in, const int* in_sizes, int n_in,
                              void* d_out, int out_size) {
    const float* x  = (const float*)d_in[0];
    const float* wt = (const float*)d_in[1];
    float* out = (float*)d_out;

    k_absmean_x<<<NB * 16, 256>>>(x);
    k_megaprep<<<6994, 256>>>(x, wt);

    static int smem_set = 0;
    if (!smem_set) {
        cudaFuncSetAttribute(k_hybrid, cudaFuncAttributeMaxDynamicSharedMemorySize, SMEMH);
        smem_set = 1;
    }
    k_hybrid<<<NTILES, 512, SMEMH>>>(out);
}

// round 13
// speedup vs baseline: 2.2897x; 1.0571x over previous
#include <cuda_runtime.h>
#include <stdint.h>

#define NB     32
#define CIN    256
#define HDIM   56
#define HW     3136
#define PIXI   100352
#define OC     256
#define HP     58
#define IMGP   (HP*HP)          // 3364
#define NPAD   (NB*IMGP)        // 107648 = 841*128
#define GUARD  72
#define XROWS  (NPAD + 2*GUARD)
#define KTOT   2304
#define NTILES (NPAD/128)       // 841
#define NCHUNK 9
#define OSP    160              // popcount covers o[0,160)
#define OCI    96               // imma covers o[160,256)
#define CH_A   32768            // 128 rows * 256B
#define CH_B   (OCI*256)        // 24576
#define STG2   (CH_A + CH_B)    // 57344
#define WS_OFF  (3*STG2)                // 172032
#define WP_OFF  (WS_OFF + OSP*72*4)     // 218112
#define SMM_OFF (WP_OFF + OSP*9*4)      // 223872
#define SMEMH   (SMM_OFF + 256*4)       // 224896
#define EPI_STRIDE 132

// ---- device scratch ----
__device__ float g_alpha[NB];
__device__ float g_m[OC];
__device__ float g_part2[512*8];
__device__ __align__(256) signed char g_xs[(size_t)XROWS*256];        // padded sign bytes, PRE-SWIZZLED
__device__ __align__(256) signed char g_wsp2[(size_t)NCHUNK*OCI*256]; // imma B planes, o 160..255
__device__ unsigned g_xbits[(size_t)PIXI*8];                          // bit-packed x signs
__device__ unsigned g_wbits[OC*72];                                   // bit-packed w signs
__device__ int      g_wpop[OC*9];

// ===================== helpers =====================
__device__ __forceinline__ uint32_t smem_u32(const void* p) {
    uint32_t a;
    asm("{ .reg .u64 t; cvta.to.shared.u64 t, %1; cvt.u32.u64 %0, t; }" : "=r"(a) : "l"(p));
    return a;
}
__device__ __forceinline__ void mbar_init(uint32_t a, uint32_t cnt) {
    asm volatile("mbarrier.init.shared.b64 [%0], %1;" :: "r"(a), "r"(cnt) : "memory");
}
__device__ __forceinline__ void mbar_expect_tx(uint32_t a, uint32_t tx) {
    asm volatile("mbarrier.arrive.expect_tx.shared.b64 _, [%0], %1;" :: "r"(a), "r"(tx) : "memory");
}
__device__ __forceinline__ void mbar_arrive(uint32_t a) {
    asm volatile("mbarrier.arrive.shared.b64 _, [%0];" :: "r"(a) : "memory");
}
__device__ __forceinline__ void mbar_wait(uint32_t a, uint32_t ph) {
    asm volatile(
        "{ .reg .pred P;\n"
        "WL_%=: mbarrier.try_wait.parity.acquire.cta.shared::cta.b64 P, [%0], %1, 0x989680;\n"
        "@P bra WD_%=;\n"
        "bra WL_%=;\n"
        "WD_%=: }"
        :: "r"(a), "r"(ph) : "memory");
}
__device__ __forceinline__ void bulkcp(uint32_t dst, const void* src, uint32_t bytes, uint32_t mbar) {
    asm volatile("cp.async.bulk.shared::cluster.global.mbarrier::complete_tx::bytes [%0], [%1], %2, [%3];"
                 :: "r"(dst), "l"(src), "r"(bytes), "r"(mbar) : "memory");
}
__device__ __forceinline__ void ldsm4(uint32_t (&r)[4], uint32_t addr) {
    asm volatile("ldmatrix.sync.aligned.m8n8.x4.shared.b16 {%0,%1,%2,%3}, [%4];"
                 : "=r"(r[0]), "=r"(r[1]), "=r"(r[2]), "=r"(r[3]) : "r"(addr));
}
__device__ __forceinline__ void imma_op(int* c, const uint32_t* a, uint32_t b0, uint32_t b1) {
    asm volatile("mma.sync.aligned.m16n8k32.row.col.s32.s8.s8.s32 "
                 "{%0,%1,%2,%3}, {%4,%5,%6,%7}, {%8,%9}, {%0,%1,%2,%3};"
                 : "+r"(c[0]), "+r"(c[1]), "+r"(c[2]), "+r"(c[3])
                 : "r"(a[0]), "r"(a[1]), "r"(a[2]), "r"(a[3]), "r"(b0), "r"(b1));
}

// ===================== L0: fused x pass (read x ONCE) =====================
// grid (512, 8): bx = n*16 + chunk (196 pixels), by = cg. block = 224 threads.
__global__ void k_fused_x(const float* __restrict__ x) {
    int t = threadIdx.x;
    int bx = blockIdx.x, cg = blockIdx.y;
    int n = bx >> 4, ch = bx & 15;
    bool act = (t < 196);
    int hw = ch * 196 + t;
    float s = 0.f;
    if (act) {
        const float* xp = x + ((size_t)(n * CIN + cg * 32)) * HW + hw;
        unsigned bb[8];
        unsigned word = 0u;
        #pragma unroll
        for (int q = 0; q < 8; q++) {
            unsigned wrd = 0u;
            #pragma unroll
            for (int j = 0; j < 4; j++) {
                float v = xp[(size_t)(q * 4 + j) * HW];
                s += fabsf(v);
                bool pos = (v > 0.f);
                wrd |= (pos ? 0x01u : 0xFFu) << (j * 8);
                if (pos) word |= (1u << (q * 4 + j));
            }
            bb[q] = wrd;
        }
        int h = hw / HDIM, w = hw - h * HDIM;
        size_t row = (size_t)n * IMGP + (size_t)(h + 1) * HP + (w + 1) + GUARD;
        int rb = (int)(row & 7);
        int s0 = cg * 2;
        *(uint4*)(g_xs + row * 256 + (size_t)((s0    ) ^ rb) * 16) = make_uint4(bb[0], bb[1], bb[2], bb[3]);
        *(uint4*)(g_xs + row * 256 + (size_t)((s0 + 1) ^ rb) * 16) = make_uint4(bb[4], bb[5], bb[6], bb[7]);
        g_xbits[(size_t)(n * HW + hw) * 8 + cg] = word;
    }
    // deterministic block reduction of s (7 warps)
    __shared__ float sh[7];
    #pragma unroll
    for (int d = 16; d > 0; d >>= 1) s += __shfl_down_sync(0xffffffffu, s, d);
    if ((t & 31) == 0) sh[t >> 5] = s;
    __syncthreads();
    if (t == 0) {
        float tot = 0.f;
        #pragma unroll
        for (int i = 0; i < 7; i++) tot += sh[i];
        g_part2[bx * 8 + cg] = tot;
    }
}

// ===================== L1: weights + border + alpha (722 blocks) =====================
__global__ void k_wab(const float* __restrict__ wt) {
    int bid = blockIdx.x;
    int tid = threadIdx.x;
    if (bid < 256) {
        // ---- weights: mean|w|, bit-pack, per-tap popc, imma B planes ----
        int o = bid, c = tid;
        const float* wo = wt + (size_t)o * KTOT;
        const float* woc = wo + (size_t)c * 9;
        float v[9];
        float s = 0.f;
        #pragma unroll
        for (int t = 0; t < 9; t++) { v[t] = woc[t]; s += fabsf(v[t]); }
        __shared__ float sh[8];
        __shared__ unsigned pw[72];
        #pragma unroll
        for (int d = 16; d > 0; d >>= 1) s += __shfl_down_sync(0xffffffffu, s, d);
        if ((tid & 31) == 0) sh[tid >> 5] = s;
        __syncthreads();
        if (tid == 0) {
            float t = 0.f;
            #pragma unroll
            for (int i = 0; i < 8; i++) t += sh[i];
            g_m[o] = t / (float)KTOT;
        }
        if (tid < 72) {
            int t = tid / 8, cc = tid % 8;
            unsigned word = 0u;
            #pragma unroll
            for (int j = 0; j < 32; j++)
                if (wo[(cc * 32 + j) * 9 + t] > 0.f) word |= (1u << j);
            g_wbits[o * 72 + t * 8 + cc] = word;
            pw[t * 8 + cc] = (unsigned)__popc(word);
        }
        __syncthreads();
        if (tid < 9) {
            int acc = 0;
            #pragma unroll
            for (int cc = 0; cc < 8; cc++) acc += (int)pw[tid * 8 + cc];
            g_wpop[o * 9 + tid] = acc;
        }
        if (o >= 160) {
            int ol = o - 160;
            int half = c >> 7, off = c & 127, seg = off >> 4, bb = off & 15;
            int segp = seg ^ (ol & 7);
            #pragma unroll
            for (int t = 0; t < 9; t++)
                g_wsp2[((size_t)(t * OCI + ol) * 256) + half * 128 + segp * 16 + bb] =
                    (v[t] > 0.f) ? 1 : -1;
        }
    } else if (bid < 721) {
        // ---- zero guard + border rows (swizzle-invariant) ----
        int i = (bid - 256) * 256 + tid;       // 465*256 = 7440 rows * 16 segs
        int rowi = i >> 4, seg = i & 15;
        size_t row;
        if (rowi < 2 * GUARD) {
            row = (rowi < GUARD) ? (size_t)rowi : (size_t)(GUARD + NPAD + (rowi - GUARD));
        } else {
            int idx = rowi - 2 * GUARD;
            int n = idx / 228, j = idx - n * 228;
            int hp, wp;
            if (j < 58)       { hp = 0;  wp = j; }
            else if (j < 116) { hp = 57; wp = j - 58; }
            else if (j < 172) { wp = 0;  hp = j - 116 + 1; }
            else              { wp = 57; hp = j - 172 + 1; }
            row = (size_t)GUARD + (size_t)n * IMGP + hp * HP + wp;
        }
        ((uint4*)(g_xs + row * 256))[seg] = make_uint4(0, 0, 0, 0);
    } else {
        // ---- alpha (deterministic fixed-order sum) ----
        if (tid < 32) {
            int n = tid;
            float s = 0.f;
            #pragma unroll
            for (int c = 0; c < 16; c++)
                #pragma unroll
                for (int cg = 0; cg < 8; cg++)
                    s += g_part2[(n * 16 + c) * 8 + cg];
            float a = 2.f * s / (float)(CIN * HW);
            g_alpha[n] = fmaxf(a, 1e-5f);
        }
    }
}

// ===================== L2: hybrid conv (imma o[160,256) + popcount o[0,160)) ====
__global__ void __launch_bounds__(512, 1) k_hybrid(float* __restrict__ out) {
    extern __shared__ char smem[];
    const uint32_t sb = smem_u32(smem);
    __shared__ __align__(8) unsigned long long s_bar[6];
    const uint32_t barb = smem_u32(s_bar);

    const int tid = threadIdx.x;
    const int wid = tid >> 5;
    const int lane = tid & 31;
    const int j0 = blockIdx.x * 128;

    unsigned* ws = (unsigned*)(smem + WS_OFF);
    int* wps = (int*)(smem + WP_OFF);
    float* smm = (float*)(smem + SMM_OFF);

    if (tid == 0) {
        #pragma unroll
        for (int s = 0; s < 3; s++) {
            mbar_init(barb + s * 16, 1);       // full (tx-based)
            mbar_init(barb + s * 16 + 8, 8);   // empty: 8 imma warps
        }
    }
    for (int i = tid; i < OSP * 72; i += 512) ws[i] = g_wbits[i];
    for (int i = tid; i < OSP * 9; i += 512) wps[i] = g_wpop[i];
    if (tid < 256) smm[tid] = g_m[tid];
    __syncthreads();

    if (tid == 0) {
        #pragma unroll
        for (int q = 0; q < 3; q++) {
            uint32_t full = barb + q * 16;
            mbar_expect_tx(full, STG2);
            int od = (q / 3 - 1) * HP + (q % 3 - 1);       // q<3: dh=0
            bulkcp(sb + q * STG2, g_xs + ((size_t)(GUARD + j0 + od)) * 256, CH_A, full);
            bulkcp(sb + q * STG2 + CH_A, g_wsp2 + (size_t)q * CH_B, CH_B, full);
        }
    }

    if (tid < 256) {
        // ================= IMMA half: o in [160, 256), warp tile 32x48 ==========
        const int warp_m = wid & 3;
        const int warp_n = wid >> 2;           // 0..1
        const int r16   = (lane & 7) + ((lane >> 3) & 1) * 8;
        const int khoff = ((lane >> 4) & 1) * 16;
        const int a_r0  = warp_m * 32 + r16;
        const int b_r0  = warp_n * 48 + r16;
        const int maskB = (lane & 7) * 16;

        int acc[2][6][4];
        #pragma unroll
        for (int m = 0; m < 2; m++)
            #pragma unroll
            for (int g = 0; g < 6; g++)
                #pragma unroll
                for (int k = 0; k < 4; k++) acc[m][g][k] = 0;

        #pragma unroll 1
        for (int q = 0; q < NCHUNK; q++) {
            int s = q % 3;
            mbar_wait(barb + s * 16, (uint32_t)((q / 3) & 1));
            uint32_t sA = sb + s * STG2;
            uint32_t sB = sA + CH_A;
            int od = (q / 3 - 1) * HP + (q % 3 - 1);
            int maskA = ((od + a_r0) & 7) * 16;
            #pragma unroll
            for (int ks = 0; ks < 8; ks++) {
                int half = (ks >> 2) * 128;
                int kh = (ks & 3) * 32 + khoff;
                int kxA = half + (kh ^ maskA);
                int kxB = half + (kh ^ maskB);
                uint32_t af[2][4], bf[3][4];
                ldsm4(af[0], sA + (unsigned)(a_r0 * 256) + kxA);
                ldsm4(af[1], sA + (unsigned)((a_r0 + 16) * 256) + kxA);
                ldsm4(bf[0], sB + (unsigned)(b_r0 * 256) + kxB);
                ldsm4(bf[1], sB + (unsigned)((b_r0 + 16) * 256) + kxB);
                ldsm4(bf[2], sB + (unsigned)((b_r0 + 32) * 256) + kxB);
                #pragma unroll
                for (int i = 0; i < 3; i++) {
                    imma_op(acc[0][i * 2 + 0], af[0], bf[i][0], bf[i][2]);
                    imma_op(acc[1][i * 2 + 0], af[1], bf[i][0], bf[i][2]);
                    imma_op(acc[0][i * 2 + 1], af[0], bf[i][1], bf[i][3]);
                    imma_op(acc[1][i * 2 + 1], af[1], bf[i][1], bf[i][3]);
                }
            }
            if (lane == 0) mbar_arrive(barb + s * 16 + 8);
            if (tid == 0 && q + 3 < NCHUNK) {
                int qq = q + 3;
                mbar_wait(barb + s * 16 + 8, (uint32_t)(1 - ((qq / 3) & 1)));
                uint32_t full = barb + s * 16;
                mbar_expect_tx(full, STG2);
                int od2 = (qq / 3 - 1) * HP + (qq % 3 - 1);
                bulkcp(sA, g_xs + ((size_t)(GUARD + j0 + od2)) * 256, CH_A, full);
                bulkcp(sB, g_wsp2 + (size_t)qq * CH_B, CH_B, full);
            }
        }

        // epilogue: transpose through low smem (disjoint from ws region)
        asm volatile("bar.sync 2, 256;" ::: "memory");
        float* sf = (float*)smem;                       // [96 oc][EPI_STRIDE]
        #pragma unroll
        for (int m = 0; m < 2; m++) {
            int row = warp_m * 32 + m * 16 + (lane >> 2);
            #pragma unroll
            for (int g = 0; g < 6; g++) {
                int col = warp_n * 48 + (g >> 1) * 16 + (g & 1) * 8 + (lane & 3) * 2;
                sf[(col    ) * EPI_STRIDE + row    ] = (float)acc[m][g][0];
                sf[(col + 1) * EPI_STRIDE + row    ] = (float)acc[m][g][1];
                sf[(col    ) * EPI_STRIDE + row + 8] = (float)acc[m][g][2];
                sf[(col + 1) * EPI_STRIDE + row + 8] = (float)acc[m][g][3];
            }
        }
        asm volatile("bar.sync 2, 256;" ::: "memory");

        int p_local = tid & 127, halfq = tid >> 7;      // 2 halves x 48 oc
        int j = j0 + p_local;
        int n = j / IMGP, rem = j - n * IMGP;
        int hp = rem / HP, wq = rem - hp * HP;
        bool inter = (hp >= 1 && hp <= 56 && wq >= 1 && wq <= 56);
        float av = g_alpha[n];
        float* ob = out + ((size_t)n * OC + 160) * HW + (hp - 1) * HDIM + (wq - 1);
        #pragma unroll 4
        for (int oo = 0; oo < 48; oo++) {
            int ol = halfq * 48 + oo;
            float v = sf[ol * EPI_STRIDE + p_local] * av * smm[160 + ol];
            if (inter) ob[(size_t)ol * HW] = v;
        }
    } else {
        // ================= popcount half: o in [0, 160) =================
        int t = tid - 256;
        int px = t & 127;
        int og = t >> 7;                               // 0/1 -> o 0..79 / 80..159
        int j = j0 + px;
        int n = j / IMGP, rem = j - n * IMGP;
        int hp = rem / HP, wq = rem - hp * HP;
        if (hp >= 1 && hp <= 56 && wq >= 1 && wq <= 56) {
            int h = hp - 1, w = wq - 1;
            unsigned xb[72];
            unsigned invmask = 0u;
            #pragma unroll
            for (int tp = 0; tp < 9; tp++) {
                int hh = h + tp / 3 - 1;
                int ww = w + tp % 3 - 1;
                if (hh >= 0 && hh < HDIM && ww >= 0 && ww < HDIM) {
                    const uint4* src = (const uint4*)&g_xbits[((size_t)(n * HW + hh * HDIM + ww)) * 8];
                    uint4 a = src[0], b = src[1];
                    xb[tp*8+0]=a.x; xb[tp*8+1]=a.y; xb[tp*8+2]=a.z; xb[tp*8+3]=a.w;
                    xb[tp*8+4]=b.x; xb[tp*8+5]=b.y; xb[tp*8+6]=b.z; xb[tp*8+7]=b.w;
                } else {
                    invmask |= (1u << tp);
                    #pragma unroll
                    for (int cc = 0; cc < 8; cc++) xb[tp*8+cc] = 0u;
                }
            }
            float av = g_alpha[n];
            float* op = out + ((size_t)n * OC) * HW + h * HDIM + w;
            int o_end = og * 80 + 80;
            for (int o = og * 80; o < o_end; o++) {
                const uint4* wr = (const uint4*)&ws[o * 72];
                int acc = 0;
                #pragma unroll
                for (int q = 0; q < 18; q++) {
                    uint4 v = wr[q];
                    acc += __popc(xb[q*4+0] ^ v.x) + __popc(xb[q*4+1] ^ v.y)
                         + __popc(xb[q*4+2] ^ v.z) + __popc(xb[q*4+3] ^ v.w);
                }
                int dot = KTOT - 2 * acc;
                if (invmask) {
                    unsigned mm = invmask;
                    while (mm) {
                        int tp = __ffs(mm) - 1; mm &= mm - 1;
                        dot -= (256 - 2 * wps[o * 9 + tp]);
                    }
                }
                op[(size_t)o * HW] = av * smm[o] * (float)dot;
            }
        }
    }
}

// ===================== launch =====================
extern "C" void kernel_launch(void* const* d_in, const int* in_sizes, int n_in,
                              void* d_out, int out_size) {
    const float* x  = (const float*)d_in[0];
    const float* wt = (const float*)d_in[1];
    float* out = (float*)d_out;

    k_fused_x<<<dim3(512, 8), 224>>>(x);
    k_wab<<<722, 256>>>(wt);

    static int smem_set = 0;
    if (!smem_set) {
        cudaFuncSetAttribute(k_hybrid, cudaFuncAttributeMaxDynamicSharedMemorySize, SMEMH);
        smem_set = 1;
    }
    k_hybrid<<<NTILES, 512, SMEMH>>>(out);
}

// round 15
// speedup vs baseline: 2.4286x; 1.0607x over previous
#include <cuda_runtime.h>
#include <stdint.h>

#define NB     32
#define CIN    256
#define HDIM   56
#define HW     3136
#define PIXI   100352
#define OC     256
#define HP     58
#define IMGP   (HP*HP)          // 3364
#define NPAD   (NB*IMGP)        // 107648 = 841*128
#define GUARD  72
#define XROWS  (NPAD + 2*GUARD)
#define KTOT   2304
#define NTILES (NPAD/128)       // 841
#define NCHUNK 9
#define OSP    176              // popcount covers o[0,176)
#define OCI    80               // imma covers o[176,256)
#define CH_A   32768            // 128 rows * 256B
#define CH_B   (OCI*256)        // 20480
#define STG2   (CH_A + CH_B)    // 53248
#define WS_OFF  (3*STG2)                // 159744
#define WP_OFF  (WS_OFF + OSP*72*4)     // 210432
#define SMM_OFF (WP_OFF + OSP*9*4)      // 216768
#define SMEMH   (SMM_OFF + 256*4)       // 217792
#define EPI_STRIDE 132

// ---- device scratch ----
__device__ float g_alpha[NB];
__device__ float g_m[OC];
__device__ float g_part2[512*8];
__device__ __align__(256) signed char g_xs[(size_t)XROWS*256];        // padded sign bytes, PRE-SWIZZLED
__device__ __align__(256) signed char g_wsp2[(size_t)NCHUNK*OCI*256]; // imma B planes, o 176..255
__device__ unsigned g_xbits[(size_t)PIXI*8];                          // bit-packed x signs
__device__ unsigned g_wbits[OC*72];                                   // bit-packed w signs
__device__ int      g_wpop[OC*9];

// ===================== helpers =====================
__device__ __forceinline__ uint32_t smem_u32(const void* p) {
    uint32_t a;
    asm("{ .reg .u64 t; cvta.to.shared.u64 t, %1; cvt.u32.u64 %0, t; }" : "=r"(a) : "l"(p));
    return a;
}
__device__ __forceinline__ void mbar_init(uint32_t a, uint32_t cnt) {
    asm volatile("mbarrier.init.shared.b64 [%0], %1;" :: "r"(a), "r"(cnt) : "memory");
}
__device__ __forceinline__ void mbar_expect_tx(uint32_t a, uint32_t tx) {
    asm volatile("mbarrier.arrive.expect_tx.shared.b64 _, [%0], %1;" :: "r"(a), "r"(tx) : "memory");
}
__device__ __forceinline__ void mbar_arrive(uint32_t a) {
    asm volatile("mbarrier.arrive.shared.b64 _, [%0];" :: "r"(a) : "memory");
}
__device__ __forceinline__ void mbar_wait(uint32_t a, uint32_t ph) {
    asm volatile(
        "{ .reg .pred P;\n"
        "WL_%=: mbarrier.try_wait.parity.acquire.cta.shared::cta.b64 P, [%0], %1, 0x989680;\n"
        "@P bra WD_%=;\n"
        "bra WL_%=;\n"
        "WD_%=: }"
        :: "r"(a), "r"(ph) : "memory");
}
__device__ __forceinline__ void bulkcp(uint32_t dst, const void* src, uint32_t bytes, uint32_t mbar) {
    asm volatile("cp.async.bulk.shared::cluster.global.mbarrier::complete_tx::bytes [%0], [%1], %2, [%3];"
                 :: "r"(dst), "l"(src), "r"(bytes), "r"(mbar) : "memory");
}
__device__ __forceinline__ void ldsm4(uint32_t (&r)[4], uint32_t addr) {
    asm volatile("ldmatrix.sync.aligned.m8n8.x4.shared.b16 {%0,%1,%2,%3}, [%4];"
                 : "=r"(r[0]), "=r"(r[1]), "=r"(r[2]), "=r"(r[3]) : "r"(addr));
}
__device__ __forceinline__ void ldsm2(uint32_t (&r)[2], uint32_t addr) {
    asm volatile("ldmatrix.sync.aligned.m8n8.x2.shared.b16 {%0,%1}, [%2];"
                 : "=r"(r[0]), "=r"(r[1]) : "r"(addr));
}
__device__ __forceinline__ void imma_op(int* c, const uint32_t* a, uint32_t b0, uint32_t b1) {
    asm volatile("mma.sync.aligned.m16n8k32.row.col.s32.s8.s8.s32 "
                 "{%0,%1,%2,%3}, {%4,%5,%6,%7}, {%8,%9}, {%0,%1,%2,%3};"
                 : "+r"(c[0]), "+r"(c[1]), "+r"(c[2]), "+r"(c[3])
                 : "r"(a[0]), "r"(a[1]), "r"(a[2]), "r"(a[3]), "r"(b0), "r"(b1));
}

// ===================== L0: fused x pass (read x ONCE) =====================
__global__ void k_fused_x(const float* __restrict__ x) {
    int t = threadIdx.x;
    int bx = blockIdx.x, cg = blockIdx.y;
    int n = bx >> 4, ch = bx & 15;
    bool act = (t < 196);
    int hw = ch * 196 + t;
    float s = 0.f;
    if (act) {
        const float* xp = x + ((size_t)(n * CIN + cg * 32)) * HW + hw;
        unsigned bb[8];
        unsigned word = 0u;
        #pragma unroll
        for (int q = 0; q < 8; q++) {
            unsigned wrd = 0u;
            #pragma unroll
            for (int j = 0; j < 4; j++) {
                float v = xp[(size_t)(q * 4 + j) * HW];
                s += fabsf(v);
                bool pos = (v > 0.f);
                wrd |= (pos ? 0x01u : 0xFFu) << (j * 8);
                if (pos) word |= (1u << (q * 4 + j));
            }
            bb[q] = wrd;
        }
        int h = hw / HDIM, w = hw - h * HDIM;
        size_t row = (size_t)n * IMGP + (size_t)(h + 1) * HP + (w + 1) + GUARD;
        int rb = (int)(row & 7);
        int s0 = cg * 2;
        *(uint4*)(g_xs + row * 256 + (size_t)((s0    ) ^ rb) * 16) = make_uint4(bb[0], bb[1], bb[2], bb[3]);
        *(uint4*)(g_xs + row * 256 + (size_t)((s0 + 1) ^ rb) * 16) = make_uint4(bb[4], bb[5], bb[6], bb[7]);
        g_xbits[(size_t)(n * HW + hw) * 8 + cg] = word;
    }
    __shared__ float sh[7];
    #pragma unroll
    for (int d = 16; d > 0; d >>= 1) s += __shfl_down_sync(0xffffffffu, s, d);
    if ((t & 31) == 0) sh[t >> 5] = s;
    __syncthreads();
    if (t == 0) {
        float tot = 0.f;
        #pragma unroll
        for (int i = 0; i < 7; i++) tot += sh[i];
        g_part2[bx * 8 + cg] = tot;
    }
}

// ===================== L1: weights + border + alpha (722 blocks) =====================
__global__ void k_wab(const float* __restrict__ wt) {
    int bid = blockIdx.x;
    int tid = threadIdx.x;
    if (bid < 256) {
        int o = bid, c = tid;
        const float* wo = wt + (size_t)o * KTOT;
        const float* woc = wo + (size_t)c * 9;
        float v[9];
        float s = 0.f;
        #pragma unroll
        for (int t = 0; t < 9; t++) { v[t] = woc[t]; s += fabsf(v[t]); }
        __shared__ float sh[8];
        __shared__ unsigned pw[72];
        #pragma unroll
        for (int d = 16; d > 0; d >>= 1) s += __shfl_down_sync(0xffffffffu, s, d);
        if ((tid & 31) == 0) sh[tid >> 5] = s;
        __syncthreads();
        if (tid == 0) {
            float t = 0.f;
            #pragma unroll
            for (int i = 0; i < 8; i++) t += sh[i];
            g_m[o] = t / (float)KTOT;
        }
        if (tid < 72) {
            int t = tid / 8, cc = tid % 8;
            unsigned word = 0u;
            #pragma unroll
            for (int j = 0; j < 32; j++)
                if (wo[(cc * 32 + j) * 9 + t] > 0.f) word |= (1u << j);
            g_wbits[o * 72 + t * 8 + cc] = word;
            pw[t * 8 + cc] = (unsigned)__popc(word);
        }
        __syncthreads();
        if (tid < 9) {
            int acc = 0;
            #pragma unroll
            for (int cc = 0; cc < 8; cc++) acc += (int)pw[tid * 8 + cc];
            g_wpop[o * 9 + tid] = acc;
        }
        if (o >= (256 - OCI)) {
            int ol = o - (256 - OCI);
            int half = c >> 7, off = c & 127, seg = off >> 4, bb = off & 15;
            int segp = seg ^ (ol & 7);
            #pragma unroll
            for (int t = 0; t < 9; t++)
                g_wsp2[((size_t)(t * OCI + ol) * 256) + half * 128 + segp * 16 + bb] =
                    (v[t] > 0.f) ? 1 : -1;
        }
    } else if (bid < 721) {
        int i = (bid - 256) * 256 + tid;
        int rowi = i >> 4, seg = i & 15;
        size_t row;
        if (rowi < 2 * GUARD) {
            row = (rowi < GUARD) ? (size_t)rowi : (size_t)(GUARD + NPAD + (rowi - GUARD));
        } else {
            int idx = rowi - 2 * GUARD;
            int n = idx / 228, j = idx - n * 228;
            int hp, wp;
            if (j < 58)       { hp = 0;  wp = j; }
            else if (j < 116) { hp = 57; wp = j - 58; }
            else if (j < 172) { wp = 0;  hp = j - 116 + 1; }
            else              { wp = 57; hp = j - 172 + 1; }
            row = (size_t)GUARD + (size_t)n * IMGP + hp * HP + wp;
        }
        ((uint4*)(g_xs + row * 256))[seg] = make_uint4(0, 0, 0, 0);
    } else {
        if (tid < 32) {
            int n = tid;
            float s = 0.f;
            #pragma unroll
            for (int c = 0; c < 16; c++)
                #pragma unroll
                for (int cg = 0; cg < 8; cg++)
                    s += g_part2[(n * 16 + c) * 8 + cg];
            float a = 2.f * s / (float)(CIN * HW);
            g_alpha[n] = fmaxf(a, 1e-5f);
        }
    }
}

// ===================== L2: hybrid conv (imma o[176,256) + popcount o[0,176)) ====
__global__ void __launch_bounds__(512, 1) k_hybrid(float* __restrict__ out) {
    extern __shared__ char smem[];
    const uint32_t sb = smem_u32(smem);
    __shared__ __align__(8) unsigned long long s_bar[6];
    const uint32_t barb = smem_u32(s_bar);

    const int tid = threadIdx.x;
    const int wid = tid >> 5;
    const int lane = tid & 31;
    const int j0 = blockIdx.x * 128;

    unsigned* ws = (unsigned*)(smem + WS_OFF);
    int* wps = (int*)(smem + WP_OFF);
    float* smm = (float*)(smem + SMM_OFF);

    if (tid == 0) {
        #pragma unroll
        for (int s = 0; s < 3; s++) {
            mbar_init(barb + s * 16, 1);
            mbar_init(barb + s * 16 + 8, 8);
        }
    }
    for (int i = tid; i < OSP * 72; i += 512) ws[i] = g_wbits[i];
    for (int i = tid; i < OSP * 9; i += 512) wps[i] = g_wpop[i];
    if (tid < 256) smm[tid] = g_m[tid];
    __syncthreads();

    if (tid == 0) {
        #pragma unroll
        for (int q = 0; q < 3; q++) {
            uint32_t full = barb + q * 16;
            mbar_expect_tx(full, STG2);
            int od = (q / 3 - 1) * HP + (q % 3 - 1);
            bulkcp(sb + q * STG2, g_xs + ((size_t)(GUARD + j0 + od)) * 256, CH_A, full);
            bulkcp(sb + q * STG2 + CH_A, g_wsp2 + (size_t)q * CH_B, CH_B, full);
        }
    }

    if (tid < 256) {
        // ======== IMMA half: o in [176, 256), warp tile 32x40 ========
        const int warp_m = wid & 3;
        const int warp_n = wid >> 2;
        const int r16   = (lane & 7) + ((lane >> 3) & 1) * 8;
        const int khoff = ((lane >> 4) & 1) * 16;
        const int a_r0  = warp_m * 32 + r16;
        const int b_r0  = warp_n * 40 + r16;
        const int maskB = (lane & 7) * 16;
        const int b2_r  = warp_n * 40 + 32 + (lane & 7);
        const int k2off = ((lane >> 3) & 1) * 16;

        int acc[2][5][4];
        #pragma unroll
        for (int m = 0; m < 2; m++)
            #pragma unroll
            for (int g = 0; g < 5; g++)
                #pragma unroll
                for (int k = 0; k < 4; k++) acc[m][g][k] = 0;

        #pragma unroll 1
        for (int q = 0; q < NCHUNK; q++) {
            int s = q % 3;
            mbar_wait(barb + s * 16, (uint32_t)((q / 3) & 1));
            uint32_t sA = sb + s * STG2;
            uint32_t sB = sA + CH_A;
            int od = (q / 3 - 1) * HP + (q % 3 - 1);
            int maskA = ((od + a_r0) & 7) * 16;
            #pragma unroll
            for (int ks = 0; ks < 8; ks++) {
                int half = (ks >> 2) * 128;
                int kh = (ks & 3) * 32 + khoff;
                int kxA = half + (kh ^ maskA);
                int kxB = half + (kh ^ maskB);
                int kxB2 = half + (((ks & 3) * 32 + k2off) ^ maskB);
                uint32_t af[2][4], bf[2][4], bf2[2];
                ldsm4(af[0], sA + (unsigned)(a_r0 * 256) + kxA);
                ldsm4(af[1], sA + (unsigned)((a_r0 + 16) * 256) + kxA);
                ldsm4(bf[0], sB + (unsigned)(b_r0 * 256) + kxB);
                ldsm4(bf[1], sB + (unsigned)((b_r0 + 16) * 256) + kxB);
                ldsm2(bf2, sB + (unsigned)(b2_r * 256) + kxB2);
                #pragma unroll
                for (int i = 0; i < 2; i++) {
                    imma_op(acc[0][i * 2 + 0], af[0], bf[i][0], bf[i][2]);
                    imma_op(acc[1][i * 2 + 0], af[1], bf[i][0], bf[i][2]);
                    imma_op(acc[0][i * 2 + 1], af[0], bf[i][1], bf[i][3]);
                    imma_op(acc[1][i * 2 + 1], af[1], bf[i][1], bf[i][3]);
                }
                imma_op(acc[0][4], af[0], bf2[0], bf2[1]);
                imma_op(acc[1][4], af[1], bf2[0], bf2[1]);
            }
            if (lane == 0) mbar_arrive(barb + s * 16 + 8);
            if (tid == 0 && q + 3 < NCHUNK) {
                int qq = q + 3;
                mbar_wait(barb + s * 16 + 8, (uint32_t)(1 - ((qq / 3) & 1)));
                uint32_t full = barb + s * 16;
                mbar_expect_tx(full, STG2);
                int od2 = (qq / 3 - 1) * HP + (qq % 3 - 1);
                bulkcp(sA, g_xs + ((size_t)(GUARD + j0 + od2)) * 256, CH_A, full);
                bulkcp(sB, g_wsp2 + (size_t)qq * CH_B, CH_B, full);
            }
        }

        // epilogue: transpose through low smem
        asm volatile("bar.sync 2, 256;" ::: "memory");
        float* sf = (float*)smem;                       // [80 oc][EPI_STRIDE]
        #pragma unroll
        for (int m = 0; m < 2; m++) {
            int row = warp_m * 32 + m * 16 + (lane >> 2);
            #pragma unroll
            for (int g = 0; g < 4; g++) {
                int col = warp_n * 40 + (g >> 1) * 16 + (g & 1) * 8 + (lane & 3) * 2;
                sf[(col    ) * EPI_STRIDE + row    ] = (float)acc[m][g][0];
                sf[(col + 1) * EPI_STRIDE + row    ] = (float)acc[m][g][1];
                sf[(col    ) * EPI_STRIDE + row + 8] = (float)acc[m][g][2];
                sf[(col + 1) * EPI_STRIDE + row + 8] = (float)acc[m][g][3];
            }
            {   // group 4 (cols +32..39)
                int col = warp_n * 40 + 32 + (lane & 3) * 2;
                sf[(col    ) * EPI_STRIDE + row    ] = (float)acc[m][4][0];
                sf[(col + 1) * EPI_STRIDE + row    ] = (float)acc[m][4][1];
                sf[(col    ) * EPI_STRIDE + row + 8] = (float)acc[m][4][2];
                sf[(col + 1) * EPI_STRIDE + row + 8] = (float)acc[m][4][3];
            }
        }
        asm volatile("bar.sync 2, 256;" ::: "memory");

        int p_local = tid & 127, halfq = tid >> 7;      // 2 halves x 40 oc
        int j = j0 + p_local;
        int n = j / IMGP, rem = j - n * IMGP;
        int hp = rem / HP, wq = rem - hp * HP;
        bool inter = (hp >= 1 && hp <= 56 && wq >= 1 && wq <= 56);
        float av = g_alpha[n];
        float* ob = out + ((size_t)n * OC + OSP) * HW + (hp - 1) * HDIM + (wq - 1);
        #pragma unroll 4
        for (int oo = 0; oo < 40; oo++) {
            int ol = halfq * 40 + oo;
            float v = sf[ol * EPI_STRIDE + p_local] * av * smm[OSP + ol];
            if (inter) ob[(size_t)ol * HW] = v;
        }
    } else {
        // ======== popcount half: o in [0, 176), 2 oc at a time, 8 acc chains ====
        int t = tid - 256;
        int px = t & 127;
        int og = t >> 7;                               // 0/1 -> o 0..87 / 88..175
        int j = j0 + px;
        int n = j / IMGP, rem = j - n * IMGP;
        int hp = rem / HP, wq = rem - hp * HP;
        if (hp >= 1 && hp <= 56 && wq >= 1 && wq <= 56) {
            int h = hp - 1, w = wq - 1;
            unsigned xb[72];
            unsigned invmask = 0u;
            #pragma unroll
            for (int tp = 0; tp < 9; tp++) {
                int hh = h + tp / 3 - 1;
                int ww = w + tp % 3 - 1;
                if (hh >= 0 && hh < HDIM && ww >= 0 && ww < HDIM) {
                    const uint4* src = (const uint4*)&g_xbits[((size_t)(n * HW + hh * HDIM + ww)) * 8];
                    uint4 a = src[0], b = src[1];
                    xb[tp*8+0]=a.x; xb[tp*8+1]=a.y; xb[tp*8+2]=a.z; xb[tp*8+3]=a.w;
                    xb[tp*8+4]=b.x; xb[tp*8+5]=b.y; xb[tp*8+6]=b.z; xb[tp*8+7]=b.w;
                } else {
                    invmask |= (1u << tp);
                    #pragma unroll
                    for (int cc = 0; cc < 8; cc++) xb[tp*8+cc] = 0u;
                }
            }
            float av = g_alpha[n];
            float* op = out + ((size_t)n * OC) * HW + h * HDIM + w;
            int o0 = og * 88;
            #pragma unroll 1
            for (int o = o0; o < o0 + 88; o += 2) {
                const uint4* wr0 = (const uint4*)&ws[o * 72];
                const uint4* wr1 = (const uint4*)&ws[(o + 1) * 72];
                int a0 = 0, a1 = 0, a2 = 0, a3 = 0;
                int b0 = 0, b1 = 0, b2 = 0, b3 = 0;
                #pragma unroll
                for (int q = 0; q < 18; q++) {
                    uint4 v0 = wr0[q], v1 = wr1[q];
                    a0 += __popc(xb[q*4+0] ^ v0.x);
                    a1 += __popc(xb[q*4+1] ^ v0.y);
                    a2 += __popc(xb[q*4+2] ^ v0.z);
                    a3 += __popc(xb[q*4+3] ^ v0.w);
                    b0 += __popc(xb[q*4+0] ^ v1.x);
                    b1 += __popc(xb[q*4+1] ^ v1.y);
                    b2 += __popc(xb[q*4+2] ^ v1.z);
                    b3 += __popc(xb[q*4+3] ^ v1.w);
                }
                int dot0 = KTOT - 2 * ((a0 + a1) + (a2 + a3));
                int dot1 = KTOT - 2 * ((b0 + b1) + (b2 + b3));
                if (invmask) {
                    unsigned mm = invmask;
                    while (mm) {
                        int tp = __ffs(mm) - 1; mm &= mm - 1;
                        dot0 -= (256 - 2 * wps[o * 9 + tp]);
                        dot1 -= (256 - 2 * wps[(o + 1) * 9 + tp]);
                    }
                }
                op[(size_t)o * HW]       = av * smm[o]     * (float)dot0;
                op[(size_t)(o + 1) * HW] = av * smm[o + 1] * (float)dot1;
            }
        }
    }
}

// ===================== launch =====================
extern "C" void kernel_launch(void* const* d_in, const int* in_sizes, int n_in,
                              void* d_out, int out_size) {
    const float* x  = (const float*)d_in[0];
    const float* wt = (const float*)d_in[1];
    float* out = (float*)d_out;

    k_fused_x<<<dim3(512, 8), 224>>>(x);
    k_wab<<<722, 256>>>(wt);

    static int smem_set = 0;
    if (!smem_set) {
        cudaFuncSetAttribute(k_hybrid, cudaFuncAttributeMaxDynamicSharedMemorySize, SMEMH);
        smem_set = 1;
    }
    k_hybrid<<<NTILES, 512, SMEMH>>>(out);
}